// round 14
// baseline (speedup 1.0000x reference)
#include <cuda_runtime.h>
#include <cuda_fp16.h>
#include <math.h>
#include <stdint.h>

#define N_GRID 4096
#define NH     2048
#define SPLITS 8
#define MAXB   1024

// ---------------- device scratch ----------------
__device__ __half g_uP_h [MAXB * NH];        // folded rho (fp16)
__device__ __half g_uM_h [MAXB * NH];
__device__ __half g_CsF_h[2 * 128 * NH];     // unscaled cos, [g][k'][n']
__device__ __half g_CsT_h[2 * NH * 128];     // unscaled cos, [g][n'][k']
__device__ float  g_part [16 * MAXB * 128];
__device__ __half g_Ae_h [MAXB * 128];       // 2*ms-scaled coeffs (fp16)
__device__ __half g_Ao_h [MAXB * 128];

// ---------------- helpers ----------------
__device__ __forceinline__ uint32_t smem_u32(const void* p) {
    uint32_t a;
    asm("{ .reg .u64 t; cvta.to.shared.u64 t, %1; cvt.u32.u64 %0, t; }" : "=r"(a) : "l"(p));
    return a;
}
__device__ __forceinline__ uint32_t swz(uint32_t off) { return off ^ ((off >> 3) & 0x70); }

__device__ __forceinline__ void cp16(uint32_t dst, const void* src) {
    asm volatile("cp.async.cg.shared.global [%0], [%1], 16;" :: "r"(dst), "l"(src));
}
__device__ __forceinline__ void cp_commit() {
    asm volatile("cp.async.commit_group;" ::: "memory");
}
template <int N>
__device__ __forceinline__ void cp_wait() {
    asm volatile("cp.async.wait_group %0;" :: "n"(N) : "memory");
}

__device__ __forceinline__ void ldsm_x4(uint32_t& r0, uint32_t& r1, uint32_t& r2, uint32_t& r3,
                                        uint32_t addr) {
    asm volatile("ldmatrix.sync.aligned.m8n8.x4.shared.b16 {%0,%1,%2,%3}, [%4];"
                 : "=r"(r0), "=r"(r1), "=r"(r2), "=r"(r3) : "r"(addr));
}
__device__ __forceinline__ void mma_f16(float* c, uint32_t a0, uint32_t a1, uint32_t a2,
                                        uint32_t a3, uint32_t b0, uint32_t b1) {
    asm volatile("mma.sync.aligned.m16n8k16.row.col.f32.f16.f16.f32 "
                 "{%0,%1,%2,%3}, {%4,%5,%6,%7}, {%8,%9}, {%0,%1,%2,%3};"
                 : "+f"(c[0]), "+f"(c[1]), "+f"(c[2]), "+f"(c[3])
                 : "r"(a0), "r"(a1), "r"(a2), "r"(a3), "r"(b0), "r"(b1));
}

union H4 { __half h[4]; uint2 v; };

// ---------------------------------------------------------------------------
__device__ __forceinline__ float cos_acc(float x) {
    const float INV_PIO2 = 0.6366197723675814f;
    float qf = rintf(x * INV_PIO2);
    int   iq = (int)qf;
    const float HI = 1.57079637050628662109375f;
    const float MD = -4.3711388286737929e-08f;
    const float LO = -1.7151245100059657e-15f;
    float r = fmaf(-qf, HI, x);
    r = fmaf(-qf, MD, r);
    r = fmaf(-qf, LO, r);
    float r2 = r * r;
    float pc = fmaf(r2,  2.4390448796e-05f, -1.3886763775e-03f);
    pc = fmaf(r2, pc,  4.1666623323e-02f);
    pc = fmaf(r2, pc, -4.9999999725e-01f);
    pc = fmaf(r2, pc,  1.0f);
    float ps = fmaf(r2,  2.7183114939e-06f, -1.9839334836e-04f);
    ps = fmaf(r2, ps,  8.3333293859e-03f);
    ps = fmaf(r2, ps, -1.6666666642e-01f);
    ps = r * fmaf(r2, ps, 1.0f);
    int n = iq & 3;
    float v = (n & 1) ? ps : pc;
    if (n == 1 || n == 2) v = -v;
    return v;
}

__device__ __forceinline__ float cs_raw(int n, int k) {
    const float PI_F = 3.1415927410125732421875f;
    float t1 = PI_F * (float)(2 * n + 1);
    float theta = (t1 * (float)k) * (1.0f / 8192.0f);
    return cos_acc(theta);
}

// ---------------------------------------------------------------------------
// prep: fold rho -> u fp16 ; build unscaled Cs tables (fp16)
// ---------------------------------------------------------------------------
__global__ void prep_kernel(const float* __restrict__ rho) {
    int bx = blockIdx.x;
    if (bx < 2048) {
        int t = bx * 256 + threadIdx.x;
        int b = t >> 9;
        int np = (t & 511) * 4;
        float4 f = *(const float4*)(rho + (size_t)b * N_GRID + np);
        float4 r = *(const float4*)(rho + (size_t)b * N_GRID + (4092 - np));
        H4 p, m;
        p.h[0] = __float2half(f.x + r.w); p.h[1] = __float2half(f.y + r.z);
        p.h[2] = __float2half(f.z + r.y); p.h[3] = __float2half(f.w + r.x);
        m.h[0] = __float2half(f.x - r.w); m.h[1] = __float2half(f.y - r.z);
        m.h[2] = __float2half(f.z - r.y); m.h[3] = __float2half(f.w - r.x);
        ((uint2*)g_uP_h)[t] = p.v;
        ((uint2*)g_uM_h)[t] = m.v;
    } else if (bx < 4096) {
        int t = (bx - 2048) * 256 + threadIdx.x;
        int g = t >> 18;
        int rem = t & 0x3FFFF;
        int kp = rem >> 11, np = rem & (NH - 1);
        int k = g ? (2 * kp + 1) : (2 * kp + 2);
        g_CsF_h[t] = __float2half(cs_raw(np, k));
    } else {
        int t = (bx - 4096) * 256 + threadIdx.x;
        int g = t >> 18;
        int rem = t & 0x3FFFF;
        int np = rem >> 7, kp = rem & 127;
        int k = g ? (2 * kp + 1) : (2 * kp + 2);
        g_CsT_h[t] = __float2half(cs_raw(np, k));
    }
}

// ---------------------------------------------------------------------------
// async tile fills for 256-thread blocks
// ---------------------------------------------------------------------------
__device__ __forceinline__ void tile128_256(uint32_t dst, const __half* src,
                                            int stride, int tid) {   // 128 rows x 64
    const int row = tid >> 1;
    const int c0 = (tid & 1) * 4;
    const char* s = (const char*)(src + (size_t)row * stride);
#pragma unroll
    for (int i = 0; i < 4; i++) {
        int ch = c0 + i;
        cp16(dst + swz((uint32_t)row * 128 + ch * 16), s + ch * 16);
    }
}
__device__ __forceinline__ void tile64_256(uint32_t dst, const __half* src,
                                           int stride, int tid) {    // 64 rows x 64
    const int row = tid >> 2;
    const int c0 = (tid & 3) * 2;
    const char* s = (const char*)(src + (size_t)row * stride);
#pragma unroll
    for (int i = 0; i < 2; i++) {
        int ch = c0 + i;
        cp16(dst + swz((uint32_t)row * 128 + ch * 16), s + ch * 16);
    }
}

// ---------------------------------------------------------------------------
// shared 64-wide K step: warp tile 32(m) x 32(n); mi=2, nj=4; paired-k16 B
// ---------------------------------------------------------------------------
__device__ __forceinline__ void g1_step(uint32_t aB, uint32_t bB, uint32_t aRow,
                                        uint32_t bRow, float acc[2][4][4]) {
#pragma unroll
    for (int kp = 0; kp < 2; kp++) {
        const uint32_t kbp = kp * 64;
        uint32_t bH[4][2][2];
#pragma unroll
        for (int nj = 0; nj < 4; nj++) {
            uint32_t off = swz(bRow + nj * 8 * 128 + kbp);
            ldsm_x4(bH[nj][0][0], bH[nj][0][1], bH[nj][1][0], bH[nj][1][1], bB + off);
        }
#pragma unroll
        for (int ks = 0; ks < 2; ks++) {
            const uint32_t kb = kbp + ks * 32;
            uint32_t aH[2][4];
#pragma unroll
            for (int mi = 0; mi < 2; mi++) {
                uint32_t off = swz(aRow + mi * 16 * 128 + kb);
                ldsm_x4(aH[mi][0], aH[mi][1], aH[mi][2], aH[mi][3], aB + off);
            }
#pragma unroll
            for (int mi = 0; mi < 2; mi++)
#pragma unroll
                for (int nj = 0; nj < 4; nj++)
                    mma_f16(acc[mi][nj], aH[mi][0], aH[mi][1], aH[mi][2], aH[mi][3],
                            bH[nj][ks][0], bH[nj][ks][1]);
        }
    }
}

// ---------------------------------------------------------------------------
// GEMM1: grid (16 mt, 2 grp, 8 sp) = 256 CTAs, 256 threads, 2 CTAs/SM.
// Out tile 64(m) x 128(n), K-chunk 256 (4 steps). 3-stage ring of 24KB
// (A 64x64 @0, B 128x64 @8192). Warps: wm=wid&1 (32 rows), wn=wid>>1 (32 cols).
// ---------------------------------------------------------------------------
#define STG1 24576
#define SMEM1_BYTES (3 * STG1)

__global__ __launch_bounds__(256, 2) void gemm1_hmma(int Brows) {
    extern __shared__ char sm[];
    const uint32_t sb = smem_u32(sm);
    const int tid = threadIdx.x, wid = tid >> 5, lane = tid & 31;
    const int wm = wid & 1, wn = wid >> 1;
    const int mt = blockIdx.x, grp = blockIdx.y, sp = blockIdx.z;
    const int k0 = sp * (NH / SPLITS);
    const int NS = (NH / SPLITS) / 64;               // 4

    float acc[2][4][4];
#pragma unroll
    for (int a = 0; a < 2; a++)
#pragma unroll
        for (int b = 0; b < 4; b++)
#pragma unroll
            for (int c = 0; c < 4; c++) acc[a][b][c] = 0.0f;

    const __half* aHsrc = (grp ? g_uM_h : g_uP_h) + (size_t)(mt * 64) * NH + k0;
    const __half* bHsrc = g_CsF_h + (size_t)grp * 128 * NH + k0;

#define G1FILL(slot, ko)                                          \
    do {                                                          \
        uint32_t st_ = sb + (slot) * STG1;                        \
        tile64_256(st_,         aHsrc + (ko), NH, tid);           \
        tile128_256(st_ + 8192, bHsrc + (ko), NH, tid);           \
        cp_commit();                                              \
    } while (0)

    const uint32_t aRow = (uint32_t)(wm * 32 + (lane & 15)) * 128 + ((lane >> 4) << 4);
    const uint32_t bRow = (uint32_t)(wn * 32 + (lane & 7)) * 128 + (((lane >> 3) & 1) << 4)
                          + ((lane >> 4) & 1) * 32;

    G1FILL(0, 0);
    G1FILL(1, 64);
    for (int s = 0; s < NS; s++) {
        if (s + 1 < NS) cp_wait<1>(); else cp_wait<0>();
        __syncthreads();
        if (s + 2 < NS) {
            int slot = (s + 2) % 3;
            G1FILL(slot, (s + 2) * 64);
        }
        uint32_t st = sb + (s % 3) * STG1;
        g1_step(st, st + 8192, aRow, bRow, acc);
        __syncthreads();
    }

    const int g = lane >> 2, tig = lane & 3;
    const int mbase = mt * 64 + wm * 32;
    const int nbase = wn * 32;
#pragma unroll
    for (int mi = 0; mi < 2; mi++)
#pragma unroll
        for (int nj = 0; nj < 4; nj++) {
            int row = mbase + mi * 16 + g;
            int col = nbase + nj * 8 + tig * 2;
            float* p0 = g_part + ((size_t)(grp * SPLITS + sp) * Brows + row) * 128 + col;
            *(float2*)p0             = make_float2(acc[mi][nj][0], acc[mi][nj][1]);
            *(float2*)(p0 + 8 * 128) = make_float2(acc[mi][nj][2], acc[mi][nj][3]);
        }
}

// reduce splits + lam scale; 2.0 = SCALE^2*4096 folded here; epilogue /4096.
__global__ void reduce_lam_kernel(const float* __restrict__ ms, int Brows) {
    int g = blockIdx.y;
    int idx = blockIdx.x * blockDim.x + threadIdx.x;
    int kp = idx & 127;
    float sum = 0.0f;
#pragma unroll
    for (int s = 0; s < SPLITS; s++)
        sum += g_part[(size_t)(g * SPLITS + s) * Brows * 128 + idx];
    float v = 2.0f * ms[g ? (2 * kp) : (2 * kp + 1)] * sum;
    if (g) g_Ao_h[idx] = __float2half(v);
    else   g_Ae_h[idx] = __float2half(v);
}

// ---------------------------------------------------------------------------
// GEMM2: grid (8 mt, 32 nt) = 256 CTAs, 256 threads, 2 CTAs/SM.
// Out: 128 rows x 64 n'-cols (dual e/o -> 128 phi cols). Fully resident:
// A 64KB @0 (eo*32768 + kc*16384), B 32KB @65536 (eo*16384 + kc*8192,
// 64 n'rows x 64 k'). h-loop 2 x 32 cols; warp (wm 0..3, wn 0..1) 32x16
// dual-e/o, acc 32 floats. ONE barrier.
// ---------------------------------------------------------------------------
#define B2_BASE 65536
#define SMEM2_BYTES 98304

__global__ __launch_bounds__(256, 2) void gemm2_hmma(float* __restrict__ phi) {
    extern __shared__ char sm[];
    const uint32_t sb = smem_u32(sm);
    const int tid = threadIdx.x, wid = tid >> 5, lane = tid & 31;
    const int wm = wid & 3, wn = wid >> 2;
    const int mt = blockIdx.x, nt = blockIdx.y;
    const float OSC = 1.0f / 4096.0f;

    {
        const size_t aoff = (size_t)(mt * 128) * 128;
#pragma unroll
        for (int kc = 0; kc < 2; kc++) {
            tile128_256(sb +          kc * 16384, g_Ae_h + aoff + kc * 64, 128, tid);
            tile128_256(sb + 32768 +  kc * 16384, g_Ao_h + aoff + kc * 64, 128, tid);
        }
#pragma unroll
        for (int eo = 0; eo < 2; eo++)
#pragma unroll
            for (int kc = 0; kc < 2; kc++) {
                size_t boff = (size_t)eo * NH * 128 + (size_t)(nt * 64) * 128 + kc * 64;
                tile64_256(sb + B2_BASE + eo * 16384u + kc * 8192u, g_CsT_h + boff, 128, tid);
            }
        cp_commit();
    }

    const uint32_t aRow = (uint32_t)(wm * 32 + (lane & 15)) * 128 + ((lane >> 4) << 4);
    const int g = lane >> 2, tig = lane & 3;

    cp_wait<0>();
    __syncthreads();

    for (int h = 0; h < 2; h++) {
        // B rows within the 64-row tile: h*32 + wn*16 + nj*8 (+ lane bits)
        const uint32_t bRow = (uint32_t)(h * 32 + wn * 16 + (lane & 7)) * 128
                              + (((lane >> 3) & 1) << 4) + ((lane >> 4) & 1) * 32;

        float acc[2][2][2][4];                       // [eo][mi][nj][4]
#pragma unroll
        for (int e = 0; e < 2; e++)
#pragma unroll
            for (int a = 0; a < 2; a++)
#pragma unroll
                for (int b = 0; b < 2; b++)
#pragma unroll
                    for (int c = 0; c < 4; c++) acc[e][a][b][c] = 0.0f;

#pragma unroll
        for (int kc = 0; kc < 2; kc++) {
#pragma unroll
            for (int kp = 0; kp < 2; kp++) {
                const uint32_t kbp = kp * 64;
#pragma unroll
                for (int eo = 0; eo < 2; eo++) {
                    uint32_t aBase = sb + eo * 32768u + kc * 16384u;
                    uint32_t bBase = sb + B2_BASE + eo * 16384u + kc * 8192u;
                    uint32_t bH[2][2][2];
#pragma unroll
                    for (int nj = 0; nj < 2; nj++) {
                        uint32_t off = swz(bRow + nj * 8 * 128 + kbp);
                        ldsm_x4(bH[nj][0][0], bH[nj][0][1], bH[nj][1][0], bH[nj][1][1], bBase + off);
                    }
#pragma unroll
                    for (int ks = 0; ks < 2; ks++) {
                        const uint32_t kb = kbp + ks * 32;
                        uint32_t aH[2][4];
#pragma unroll
                        for (int mi = 0; mi < 2; mi++) {
                            uint32_t off = swz(aRow + mi * 16 * 128 + kb);
                            ldsm_x4(aH[mi][0], aH[mi][1], aH[mi][2], aH[mi][3], aBase + off);
                        }
#pragma unroll
                        for (int mi = 0; mi < 2; mi++)
#pragma unroll
                            for (int nj = 0; nj < 2; nj++)
                                mma_f16(acc[eo][mi][nj], aH[mi][0], aH[mi][1], aH[mi][2], aH[mi][3],
                                        bH[nj][ks][0], bH[nj][ks][1]);
                    }
                }
            }
        }

        // register epilogue: phi[n'] = (e+o)/4096 ; phi[4095-n'] = (e-o)/4096
#pragma unroll
        for (int mi = 0; mi < 2; mi++)
#pragma unroll
            for (int nj = 0; nj < 2; nj++) {
#pragma unroll
                for (int half = 0; half < 2; half++) {
                    int row = mt * 128 + wm * 32 + mi * 16 + half * 8 + g;
                    int c = nt * 64 + h * 32 + wn * 16 + nj * 8 + tig * 2;
                    float e0 = acc[0][mi][nj][half * 2];
                    float e1 = acc[0][mi][nj][half * 2 + 1];
                    float o0 = acc[1][mi][nj][half * 2];
                    float o1 = acc[1][mi][nj][half * 2 + 1];
                    float* rowp = phi + (size_t)row * N_GRID;
                    *(float2*)(rowp + c) = make_float2((e0 + o0) * OSC, (e1 + o1) * OSC);
                    *(float2*)(rowp + (4094 - c)) = make_float2((e1 - o1) * OSC, (e0 - o0) * OSC);
                }
            }
    }
}

// ---------------------------------------------------------------------------
extern "C" void kernel_launch(void* const* d_in, const int* in_sizes, int n_in,
                              void* d_out, int out_size) {
    const float* rho = (const float*)d_in[0];
    const float* ms  = (const float*)d_in[1];
    float* phi = (float*)d_out;
    const int Brows = in_sizes[0] / N_GRID;

    cudaFuncSetAttribute(gemm1_hmma, cudaFuncAttributeMaxDynamicSharedMemorySize, SMEM1_BYTES);
    cudaFuncSetAttribute(gemm2_hmma, cudaFuncAttributeMaxDynamicSharedMemorySize, SMEM2_BYTES);

    prep_kernel<<<6144, 256>>>(rho);

    dim3 g1(Brows / 64, 2, SPLITS);
    gemm1_hmma<<<g1, 256, SMEM1_BYTES>>>(Brows);

    dim3 gr((Brows * 128) / 256, 2);
    reduce_lam_kernel<<<gr, 256>>>(ms, Brows);

    dim3 g2(Brows / 128, NH / 64);
    gemm2_hmma<<<g2, 256, SMEM2_BYTES>>>(phi);
}

// round 15
// speedup vs baseline: 1.0837x; 1.0837x over previous
#include <cuda_runtime.h>
#include <cuda_fp16.h>
#include <math.h>
#include <stdint.h>

#define N_GRID 4096
#define NH     2048
#define SPLITS 8
#define MAXB   1024

// ---------------- device scratch ----------------
__device__ __half g_uP_h [MAXB * NH];        // folded rho (fp16)
__device__ __half g_uM_h [MAXB * NH];
__device__ __half g_CsF_h[2 * 128 * NH];     // unscaled cos, [g][k'][n']
__device__ __half g_CsT_h[2 * NH * 128];     // unscaled cos, [g][n'][k']
__device__ float  g_part [16 * MAXB * 128];
__device__ __half g_Ae_h [MAXB * 128];       // 2*ms-scaled coeffs (fp16)
__device__ __half g_Ao_h [MAXB * 128];

// ---------------- helpers ----------------
__device__ __forceinline__ uint32_t smem_u32(const void* p) {
    uint32_t a;
    asm("{ .reg .u64 t; cvta.to.shared.u64 t, %1; cvt.u32.u64 %0, t; }" : "=r"(a) : "l"(p));
    return a;
}
__device__ __forceinline__ uint32_t swz(uint32_t off) { return off ^ ((off >> 3) & 0x70); }

__device__ __forceinline__ void cp16(uint32_t dst, const void* src) {
    asm volatile("cp.async.cg.shared.global [%0], [%1], 16;" :: "r"(dst), "l"(src));
}
__device__ __forceinline__ void cp_commit() {
    asm volatile("cp.async.commit_group;" ::: "memory");
}
template <int N>
__device__ __forceinline__ void cp_wait() {
    asm volatile("cp.async.wait_group %0;" :: "n"(N) : "memory");
}

__device__ __forceinline__ void ldsm_x4(uint32_t& r0, uint32_t& r1, uint32_t& r2, uint32_t& r3,
                                        uint32_t addr) {
    asm volatile("ldmatrix.sync.aligned.m8n8.x4.shared.b16 {%0,%1,%2,%3}, [%4];"
                 : "=r"(r0), "=r"(r1), "=r"(r2), "=r"(r3) : "r"(addr));
}
__device__ __forceinline__ void mma_f16(float* c, uint32_t a0, uint32_t a1, uint32_t a2,
                                        uint32_t a3, uint32_t b0, uint32_t b1) {
    asm volatile("mma.sync.aligned.m16n8k16.row.col.f32.f16.f16.f32 "
                 "{%0,%1,%2,%3}, {%4,%5,%6,%7}, {%8,%9}, {%0,%1,%2,%3};"
                 : "+f"(c[0]), "+f"(c[1]), "+f"(c[2]), "+f"(c[3])
                 : "r"(a0), "r"(a1), "r"(a2), "r"(a3), "r"(b0), "r"(b1));
}

union H4 { __half h[4]; uint2 v; };

// ---------------------------------------------------------------------------
__device__ __forceinline__ float cos_acc(float x) {
    const float INV_PIO2 = 0.6366197723675814f;
    float qf = rintf(x * INV_PIO2);
    int   iq = (int)qf;
    const float HI = 1.57079637050628662109375f;
    const float MD = -4.3711388286737929e-08f;
    const float LO = -1.7151245100059657e-15f;
    float r = fmaf(-qf, HI, x);
    r = fmaf(-qf, MD, r);
    r = fmaf(-qf, LO, r);
    float r2 = r * r;
    float pc = fmaf(r2,  2.4390448796e-05f, -1.3886763775e-03f);
    pc = fmaf(r2, pc,  4.1666623323e-02f);
    pc = fmaf(r2, pc, -4.9999999725e-01f);
    pc = fmaf(r2, pc,  1.0f);
    float ps = fmaf(r2,  2.7183114939e-06f, -1.9839334836e-04f);
    ps = fmaf(r2, ps,  8.3333293859e-03f);
    ps = fmaf(r2, ps, -1.6666666642e-01f);
    ps = r * fmaf(r2, ps, 1.0f);
    int n = iq & 3;
    float v = (n & 1) ? ps : pc;
    if (n == 1 || n == 2) v = -v;
    return v;
}

__device__ __forceinline__ float cs_raw(int n, int k) {
    const float PI_F = 3.1415927410125732421875f;
    float t1 = PI_F * (float)(2 * n + 1);
    float theta = (t1 * (float)k) * (1.0f / 8192.0f);
    return cos_acc(theta);
}

// ---------------------------------------------------------------------------
// prep: fold rho -> u fp16 ; build unscaled Cs tables (fp16)
// ---------------------------------------------------------------------------
__global__ void prep_kernel(const float* __restrict__ rho) {
    int bx = blockIdx.x;
    if (bx < 2048) {
        int t = bx * 256 + threadIdx.x;
        int b = t >> 9;
        int np = (t & 511) * 4;
        float4 f = *(const float4*)(rho + (size_t)b * N_GRID + np);
        float4 r = *(const float4*)(rho + (size_t)b * N_GRID + (4092 - np));
        H4 p, m;
        p.h[0] = __float2half(f.x + r.w); p.h[1] = __float2half(f.y + r.z);
        p.h[2] = __float2half(f.z + r.y); p.h[3] = __float2half(f.w + r.x);
        m.h[0] = __float2half(f.x - r.w); m.h[1] = __float2half(f.y - r.z);
        m.h[2] = __float2half(f.z - r.y); m.h[3] = __float2half(f.w - r.x);
        ((uint2*)g_uP_h)[t] = p.v;
        ((uint2*)g_uM_h)[t] = m.v;
    } else if (bx < 4096) {
        int t = (bx - 2048) * 256 + threadIdx.x;
        int g = t >> 18;
        int rem = t & 0x3FFFF;
        int kp = rem >> 11, np = rem & (NH - 1);
        int k = g ? (2 * kp + 1) : (2 * kp + 2);
        g_CsF_h[t] = __float2half(cs_raw(np, k));
    } else {
        int t = (bx - 4096) * 256 + threadIdx.x;
        int g = t >> 18;
        int rem = t & 0x3FFFF;
        int np = rem >> 7, kp = rem & 127;
        int k = g ? (2 * kp + 1) : (2 * kp + 2);
        g_CsT_h[t] = __float2half(cs_raw(np, k));
    }
}

// ---------------------------------------------------------------------------
__device__ __forceinline__ void tile_async(uint32_t dst, const __half* src,
                                           int stride, int tid) {          // 128x64
    const int row = tid >> 2;
    const int c0 = tid & 3;
    const char* s = (const char*)(src + (size_t)row * stride);
#pragma unroll
    for (int i = 0; i < 2; i++) {
        int ch = c0 + i * 4;
        cp16(dst + swz((uint32_t)row * 128 + ch * 16), s + ch * 16);
    }
}

// ---------------------------------------------------------------------------
// GEMM1 (R13, unchanged): single-term, 3-stage ring, grid (8,2,8), 512 thr.
// ---------------------------------------------------------------------------
__device__ __forceinline__ void g1_step(uint32_t aB, uint32_t bB, uint32_t aRow,
                                        uint32_t bRow, float acc[2][4][4]) {
#pragma unroll
    for (int kp = 0; kp < 2; kp++) {
        const uint32_t kbp = kp * 64;
        uint32_t bH[4][2][2];
#pragma unroll
        for (int nj = 0; nj < 4; nj++) {
            uint32_t off = swz(bRow + nj * 8 * 128 + kbp);
            ldsm_x4(bH[nj][0][0], bH[nj][0][1], bH[nj][1][0], bH[nj][1][1], bB + off);
        }
#pragma unroll
        for (int ks = 0; ks < 2; ks++) {
            const uint32_t kb = kbp + ks * 32;
            uint32_t aH[2][4];
#pragma unroll
            for (int mi = 0; mi < 2; mi++) {
                uint32_t off = swz(aRow + mi * 16 * 128 + kb);
                ldsm_x4(aH[mi][0], aH[mi][1], aH[mi][2], aH[mi][3], aB + off);
            }
#pragma unroll
            for (int mi = 0; mi < 2; mi++)
#pragma unroll
                for (int nj = 0; nj < 4; nj++)
                    mma_f16(acc[mi][nj], aH[mi][0], aH[mi][1], aH[mi][2], aH[mi][3],
                            bH[nj][ks][0], bH[nj][ks][1]);
        }
    }
}

#define STG1 32768
#define SMEM1_BYTES (3 * STG1)

__global__ __launch_bounds__(512) void gemm1_hmma(int Brows) {
    extern __shared__ char sm[];
    const uint32_t sb = smem_u32(sm);
    const int tid = threadIdx.x, wid = tid >> 5, lane = tid & 31;
    const int wm = wid & 3, wn = wid >> 2;
    const int mt = blockIdx.x, grp = blockIdx.y, sp = blockIdx.z;
    const int k0 = sp * (NH / SPLITS);
    const int NS = (NH / SPLITS) / 64;               // 4

    float acc[2][4][4];
#pragma unroll
    for (int a = 0; a < 2; a++)
#pragma unroll
        for (int b = 0; b < 4; b++)
#pragma unroll
            for (int c = 0; c < 4; c++) acc[a][b][c] = 0.0f;

    const __half* aHsrc = (grp ? g_uM_h : g_uP_h) + (size_t)(mt * 128) * NH + k0;
    const __half* bHsrc = g_CsF_h + (size_t)grp * 128 * NH + k0;

#define G1FILL(slot, ko)                                          \
    do {                                                          \
        uint32_t st_ = sb + (slot) * STG1;                        \
        tile_async(st_,         aHsrc + (ko), NH, tid);           \
        tile_async(st_ + 16384, bHsrc + (ko), NH, tid);           \
        cp_commit();                                              \
    } while (0)

    const uint32_t aRow = (uint32_t)(wm * 32 + (lane & 15)) * 128 + ((lane >> 4) << 4);
    const uint32_t bRow = (uint32_t)(wn * 32 + (lane & 7)) * 128 + (((lane >> 3) & 1) << 4)
                          + ((lane >> 4) & 1) * 32;

    G1FILL(0, 0);
    G1FILL(1, 64);
    for (int s = 0; s < NS; s++) {
        if (s + 1 < NS) cp_wait<1>(); else cp_wait<0>();
        __syncthreads();
        if (s + 2 < NS) {
            int slot = (s + 2) % 3;
            G1FILL(slot, (s + 2) * 64);
        }
        uint32_t st = sb + (s % 3) * STG1;
        g1_step(st, st + 16384, aRow, bRow, acc);
    }

    const int g = lane >> 2, tig = lane & 3;
    const int mbase = mt * 128 + wm * 32;
    const int nbase = wn * 32;
#pragma unroll
    for (int mi = 0; mi < 2; mi++)
#pragma unroll
        for (int nj = 0; nj < 4; nj++) {
            int row = mbase + mi * 16 + g;
            int col = nbase + nj * 8 + tig * 2;
            float* p0 = g_part + ((size_t)(grp * SPLITS + sp) * Brows + row) * 128 + col;
            *(float2*)p0             = make_float2(acc[mi][nj][0], acc[mi][nj][1]);
            *(float2*)(p0 + 8 * 128) = make_float2(acc[mi][nj][2], acc[mi][nj][3]);
        }
}

// reduce splits + lam scale; 2.0 = SCALE^2*4096 folded here; epilogue /4096.
__global__ void reduce_lam_kernel(const float* __restrict__ ms, int Brows) {
    int g = blockIdx.y;
    int idx = blockIdx.x * blockDim.x + threadIdx.x;
    int kp = idx & 127;
    float sum = 0.0f;
#pragma unroll
    for (int s = 0; s < SPLITS; s++)
        sum += g_part[(size_t)(g * SPLITS + s) * Brows * 128 + idx];
    float v = 2.0f * ms[g ? (2 * kp) : (2 * kp + 1)] * sum;
    if (g) g_Ao_h[idx] = __float2half(v);
    else   g_Ae_h[idx] = __float2half(v);
}

// ---------------------------------------------------------------------------
// GEMM2 v7: R13 layout (A 64KB @0: eo*32768+kc*16384; B 64KB @65536 same idx),
// grid (8,16), 512 thr, h-loop 2 x 64 cols, warp 32x16 dual-e/o.
// NEW: 8-unit (kc,kp,eo) mainloop with 2-deep REGISTER pipeline:
// LDSMs of unit u+1 issued before MMAs of unit u. Per-acc MMA order
// identical to R13 -> bit-identical phi.
// ---------------------------------------------------------------------------
#define B2_BASE 65536
#define SMEM2_BYTES 131072

__global__ __launch_bounds__(512) void gemm2_hmma(float* __restrict__ phi) {
    extern __shared__ char sm[];
    const uint32_t sb = smem_u32(sm);
    const int tid = threadIdx.x, wid = tid >> 5, lane = tid & 31;
    const int wm = wid & 3, wn = wid >> 2;
    const int mt = blockIdx.x, nt = blockIdx.y;
    const float OSC = 1.0f / 4096.0f;

    {
        const size_t aoff = (size_t)(mt * 128) * 128;
#pragma unroll
        for (int kc = 0; kc < 2; kc++) {
            tile_async(sb +          kc * 16384, g_Ae_h + aoff + kc * 64, 128, tid);
            tile_async(sb + 32768 +  kc * 16384, g_Ao_h + aoff + kc * 64, 128, tid);
        }
#pragma unroll
        for (int eo = 0; eo < 2; eo++)
#pragma unroll
            for (int kc = 0; kc < 2; kc++) {
                size_t boff = (size_t)eo * NH * 128 + (size_t)(nt * 128) * 128 + kc * 64;
                tile_async(sb + B2_BASE + eo * 32768u + kc * 16384u, g_CsT_h + boff, 128, tid);
            }
        cp_commit();
    }

    const uint32_t aRow = (uint32_t)(wm * 32 + (lane & 15)) * 128 + ((lane >> 4) << 4);
    const int g = lane >> 2, tig = lane & 3;

    cp_wait<0>();
    __syncthreads();

    for (int h = 0; h < 2; h++) {
        const uint32_t bRow = (uint32_t)(h * 64 + wn * 16 + (lane & 7)) * 128
                              + (((lane >> 3) & 1) << 4) + ((lane >> 4) & 1) * 32;

        float acc[2][2][2][4];                       // [eo][mi][nj][4]
#pragma unroll
        for (int e = 0; e < 2; e++)
#pragma unroll
            for (int a = 0; a < 2; a++)
#pragma unroll
                for (int b = 0; b < 2; b++)
#pragma unroll
                    for (int c = 0; c < 4; c++) acc[e][a][b][c] = 0.0f;

        // register pipeline buffers: [buf][...]
        uint32_t fb[2][2][2][2];   // [buf][nj][ks][2]
        uint32_t fa[2][2][2][4];   // [buf][ks][mi][4]

        // unit u: kc = u>>2, kp = (u>>1)&1, eo = u&1
#define G2_LOAD(u, buf)                                                        \
        do {                                                                   \
            const int kc_ = (u) >> 2, kp_ = ((u) >> 1) & 1, eo_ = (u) & 1;     \
            const uint32_t aBase_ = sb + eo_ * 32768u + kc_ * 16384u;          \
            const uint32_t bBase_ = sb + B2_BASE + eo_ * 32768u + kc_ * 16384u;\
            const uint32_t kbp_ = kp_ * 64;                                    \
            _Pragma("unroll")                                                  \
            for (int nj = 0; nj < 2; nj++) {                                   \
                uint32_t off = swz(bRow + nj * 8 * 128 + kbp_);                \
                ldsm_x4(fb[buf][nj][0][0], fb[buf][nj][0][1],                  \
                        fb[buf][nj][1][0], fb[buf][nj][1][1], bBase_ + off);   \
            }                                                                  \
            _Pragma("unroll")                                                  \
            for (int ks = 0; ks < 2; ks++)                                     \
                _Pragma("unroll")                                              \
                for (int mi = 0; mi < 2; mi++) {                               \
                    uint32_t off = swz(aRow + mi * 16 * 128 + kbp_ + ks * 32); \
                    ldsm_x4(fa[buf][ks][mi][0], fa[buf][ks][mi][1],            \
                            fa[buf][ks][mi][2], fa[buf][ks][mi][3],            \
                            aBase_ + off);                                     \
                }                                                              \
        } while (0)

#define G2_MMA(u, buf)                                                         \
        do {                                                                   \
            const int eo_ = (u) & 1;                                           \
            _Pragma("unroll")                                                  \
            for (int ks = 0; ks < 2; ks++)                                     \
                _Pragma("unroll")                                              \
                for (int mi = 0; mi < 2; mi++)                                 \
                    _Pragma("unroll")                                          \
                    for (int nj = 0; nj < 2; nj++)                             \
                        mma_f16(acc[eo_][mi][nj],                              \
                                fa[buf][ks][mi][0], fa[buf][ks][mi][1],        \
                                fa[buf][ks][mi][2], fa[buf][ks][mi][3],        \
                                fb[buf][nj][ks][0], fb[buf][nj][ks][1]);       \
        } while (0)

        G2_LOAD(0, 0);
        G2_LOAD(1, 1); G2_MMA(0, 0);
        G2_LOAD(2, 0); G2_MMA(1, 1);
        G2_LOAD(3, 1); G2_MMA(2, 0);
        G2_LOAD(4, 0); G2_MMA(3, 1);
        G2_LOAD(5, 1); G2_MMA(4, 0);
        G2_LOAD(6, 0); G2_MMA(5, 1);
        G2_LOAD(7, 1); G2_MMA(6, 0);
        G2_MMA(7, 1);

#undef G2_LOAD
#undef G2_MMA

        // register epilogue: phi[n'] = (e+o)/4096 ; phi[4095-n'] = (e-o)/4096
#pragma unroll
        for (int mi = 0; mi < 2; mi++)
#pragma unroll
            for (int nj = 0; nj < 2; nj++) {
#pragma unroll
                for (int half = 0; half < 2; half++) {
                    int row = mt * 128 + wm * 32 + mi * 16 + half * 8 + g;
                    int c = nt * 128 + h * 64 + wn * 16 + nj * 8 + tig * 2;
                    float e0 = acc[0][mi][nj][half * 2];
                    float e1 = acc[0][mi][nj][half * 2 + 1];
                    float o0 = acc[1][mi][nj][half * 2];
                    float o1 = acc[1][mi][nj][half * 2 + 1];
                    float* rowp = phi + (size_t)row * N_GRID;
                    *(float2*)(rowp + c) = make_float2((e0 + o0) * OSC, (e1 + o1) * OSC);
                    *(float2*)(rowp + (4094 - c)) = make_float2((e1 - o1) * OSC, (e0 - o0) * OSC);
                }
            }
    }
}

// ---------------------------------------------------------------------------
extern "C" void kernel_launch(void* const* d_in, const int* in_sizes, int n_in,
                              void* d_out, int out_size) {
    const float* rho = (const float*)d_in[0];
    const float* ms  = (const float*)d_in[1];
    float* phi = (float*)d_out;
    const int Brows = in_sizes[0] / N_GRID;

    cudaFuncSetAttribute(gemm1_hmma, cudaFuncAttributeMaxDynamicSharedMemorySize, SMEM1_BYTES);
    cudaFuncSetAttribute(gemm2_hmma, cudaFuncAttributeMaxDynamicSharedMemorySize, SMEM2_BYTES);

    prep_kernel<<<6144, 256>>>(rho);

    dim3 g1(Brows / 128, 2, SPLITS);
    gemm1_hmma<<<g1, 512, SMEM1_BYTES>>>(Brows);

    dim3 gr((Brows * 128) / 256, 2);
    reduce_lam_kernel<<<gr, 256>>>(ms, Brows);

    dim3 g2(Brows / 128, NH / 64 / 2);
    gemm2_hmma<<<g2, 512, SMEM2_BYTES>>>(phi);
}